// round 3
// baseline (speedup 1.0000x reference)
#include <cuda_runtime.h>

// Problem constants (fixed by the reference):
// B=1, C=8, O=8, G=12, X=12, CH=8, CW=40, Xo=Yo=Zo=9
#define HWN   320      // CH*CW
#define NB    729      // 9*9*9 output voxels
#define OBN   56       // O*7  (ob = o*7+b)
#define KKN   216      // C*27 (k = c*27 + fi*9+fj*3+fk)
#define GON   96       // G*O
#define VOX   1728     // 12*12*12
#define OSTRIDE (VOX*HWN)         // 552960, stride of one (g,o) plane
#define QTILE (OBN*HWN)           // 17920 floats per n
#define OUT_ELEMS (GON*VOX*HWN)   // 53,084,160

typedef unsigned long long ull;

__device__ __forceinline__ ull fma2(ull a, ull b, ull c) {
    ull d; asm("fma.rn.f32x2 %0, %1, %2, %3;" : "=l"(d) : "l"(a), "l"(b), "l"(c)); return d;
}
__device__ __forceinline__ ull pack2(float lo, float hi) {
    ull d; asm("mov.b64 %0, {%1, %2};" : "=l"(d) : "f"(lo), "f"(hi)); return d;
}
__device__ __forceinline__ void unpack2(ull v, float& lo, float& hi) {
    asm("mov.b64 {%0, %1}, %2;" : "=f"(lo), "=f"(hi) : "l"(v));
}

// Scratch: Q[n][b*320+hw][o]  (52.2 MB). Layout: stage2 reads all 8 o of a tap
// with 2 LDS.128 that reinterpret directly as (o0,o1),(o2,o3),... f32x2 pairs.
__device__ __align__(16) float g_Q[NB * QTILE];

// ---------------------------------------------------------------------------
// Stage 1: register-tiled GEMM  Q[ob, hw] = sum_k W[ob,k] * X[k, hw]  per n.
// 320 threads: og = tid/80 owns obs [og*14, og*14+14) as 7 pairs,
//              hwg = tid%80 owns hw [hwg*4, hwg*4+4).
// x read straight from gmem (L1/L2-resident), prefetch distance 2 in regs.
// ---------------------------------------------------------------------------
extern "C" __global__ void __launch_bounds__(320, 2)
stage1_kernel(const float* __restrict__ x, const float* __restrict__ weight)
{
    extern __shared__ float sm1[];
    float* w_s    = sm1;                        // KKN*OBN = 12096 floats
    int*   rowoff = (int*)(w_s + KKN * OBN);    // KKN+2 ints

    const int n   = blockIdx.x;
    const int tid = threadIdx.x;

    // Reorder weight[o][c][f][b] -> w_s[k*56 + (o*7+b)]
    for (int idx = tid; idx < KKN * OBN; idx += 320) {
        int k = idx / OBN, ob = idx % OBN;
        int c = k / 27,    f  = k % 27;
        int o = ob / 7,    b  = ob % 7;
        w_s[idx] = weight[((o * 8 + c) * 27 + f) * 7 + b];
    }
    const int xi = n / 81, yj = (n / 9) % 9, zk = n % 9;
    for (int k = tid; k < KKN + 2; k += 320) {
        int kc = (k < KKN) ? k : (KKN - 1);
        int c = kc / 27, f = kc % 27;
        int fi = f / 9, fj = (f / 3) % 3, fk = f % 3;
        rowoff[k] = (((c * 12 + xi + fi) * 12 + (yj + fj)) * 12 + (zk + fk)) * HWN;
    }
    __syncthreads();

    const int og  = tid / 80;          // 0..3  (14 obs each)
    const int hwb = (tid % 80) * 4;    // hw base

    ull acc[7][4];
    #pragma unroll
    for (int j = 0; j < 7; j++)
        #pragma unroll
        for (int p = 0; p < 4; p++) acc[j][p] = 0ULL;

    float4 p0 = __ldg((const float4*)(x + rowoff[0] + hwb));
    float4 p1 = __ldg((const float4*)(x + rowoff[1] + hwb));
    for (int k = 0; k < KKN; k++) {
        float4 pn = __ldg((const float4*)(x + rowoff[k + 2] + hwb));
        ull xs0 = pack2(p0.x, p0.x), xs1 = pack2(p0.y, p0.y);
        ull xs2 = pack2(p0.z, p0.z), xs3 = pack2(p0.w, p0.w);
        const ull* wp = (const ull*)(w_s + k * OBN + og * 14);  // 7 LDS.64 bcast
        #pragma unroll
        for (int j = 0; j < 7; j++) {
            ull wv = wp[j];
            acc[j][0] = fma2(wv, xs0, acc[j][0]);
            acc[j][1] = fma2(wv, xs1, acc[j][1]);
            acc[j][2] = fma2(wv, xs2, acc[j][2]);
            acc[j][3] = fma2(wv, xs3, acc[j][3]);
        }
        p0 = p1; p1 = pn;
    }

    // Store: g_Q[n][(b*320+hw)*8 + o], o = ob/7, b = ob%7.
    float* qn = g_Q + (size_t)n * QTILE;
    #pragma unroll
    for (int j = 0; j < 7; j++) {
        int ob0 = og * 14 + 2 * j, ob1 = ob0 + 1;
        int o0 = ob0 / 7, b0 = ob0 % 7;
        int o1 = ob1 / 7, b1 = ob1 % 7;
        #pragma unroll
        for (int p = 0; p < 4; p++) {
            float lo, hi; unpack2(acc[j][p], lo, hi);
            qn[(b0 * HWN + hwb + p) * 8 + o0] = lo;
            qn[(b1 * HWN + hwb + p) * 8 + o1] = hi;
        }
    }
}

// ---------------------------------------------------------------------------
// Zero the non-interior border of the output (float4 stores).
// ---------------------------------------------------------------------------
extern "C" __global__ void zero_border_kernel(float4* __restrict__ out4)
{
    int idx = blockIdx.x * blockDim.x + threadIdx.x;
    if (idx >= OUT_ELEMS / 4) return;
    int voxel = (idx / (HWN / 4)) % VOX;
    int xx = voxel / 144, yy = (voxel / 12) % 12, zz = voxel % 12;
    bool interior = (xx >= 1 && xx <= 9 && yy >= 1 && yy <= 9 && zz >= 1 && zz <= 9);
    if (!interior) out4[idx] = make_float4(0.f, 0.f, 0.f, 0.f);
}

// ---------------------------------------------------------------------------
// Stage 2 (fused direct-write): thread = hw. Each thread computes the full
// 12g x 8o stack at its clamped (ii,jj) (T[g] is g or (g+1)%12 -> every thread
// needs all 12 groups; the gather is a static output-index rotation).
// bias_basis[go] = o, so bias folds into the acc init (rotation-invariant).
// Two g-halves of 6 to keep accs at 24 ull (48 regs) per pass.
// ---------------------------------------------------------------------------
extern "C" __global__ void __launch_bounds__(320, 2)
stage2_kernel(const float* __restrict__ bias,
              const float* __restrict__ basis,
              const int*   __restrict__ Iin,
              const int*   __restrict__ Jin,
              const int*   __restrict__ Tin,
              const int*   __restrict__ bb,
              float*       __restrict__ out)
{
    extern __shared__ char sm2raw[];
    ull*   basP = (ull*)sm2raw;                  // [k=63][g=12] duplicated pairs
    float* Qs   = (float*)(basP + 756);          // 17920 floats, [b*320+pos][o]
    float* bsum = Qs + QTILE;                    // 8

    const int n   = blockIdx.x;
    const int tid = threadIdx.x;

    {
        const float4* src = (const float4*)(g_Q + (size_t)n * QTILE);
        float4* dst = (float4*)Qs;
        for (int i = tid; i < QTILE / 4; i += 320) dst[i] = src[i];
    }
    // basis[g][b][u][v] -> basP[(b*9+uv)*12 + g], duplicated into both halves.
    for (int i = tid; i < 756; i += 320) {
        float v = basis[i];
        int g = i / 63, k = i % 63;
        basP[k * 12 + g] = pack2(v, v);
    }
    if (tid < 8) {
        // bias_basis = tile(arange(O), G) -> bias index is o.
        float s = 0.f;
        for (int i = 0; i < 27; i++) s += bias[tid * 27 + i];
        bsum[tid] = s;
    }
    __syncthreads();

    const int ii = __ldg(Iin + tid) - 1;          // clip(h,1,6)-1  in [0,5]
    const int jj = __ldg(Jin + tid) - 1;          // clip(w,1,38)-1 in [0,37]
    const bool border = (__ldg(Tin + tid) != 0);  // T[g=0] is 1 on border, 0 inside

    const float* qbase = Qs + (ii * 40 + jj) * 8;
    ull binit[4];
    #pragma unroll
    for (int p = 0; p < 4; p++) binit[p] = pack2(bsum[2 * p], bsum[2 * p + 1]);

    const int xi = n / 81, yj = (n / 9) % 9, zk = n % 9;
    const int voxel = (1 + xi) * 144 + (1 + yj) * 12 + (1 + zk);
    float* obase = out + (size_t)voxel * HWN + tid;

    #pragma unroll 1
    for (int gh = 0; gh < 2; gh++) {
        ull acc[6][4];
        #pragma unroll
        for (int g = 0; g < 6; g++)
            #pragma unroll
            for (int p = 0; p < 4; p++) acc[g][p] = binit[p];

        #pragma unroll 1
        for (int b = 0; b < 7; b++) {
            const float* qb = qbase + b * (HWN * 8);
            const ull*   bp = basP + b * 108 + gh * 6;   // b*9*12
            #pragma unroll
            for (int uv = 0; uv < 9; uv++) {
                int u = uv / 3, v = uv - u * 3;
                const ulonglong2* q4 = (const ulonglong2*)(qb + (u * 40 + v) * 8);
                ulonglong2 qA = q4[0];   // o pairs (0,1),(2,3)
                ulonglong2 qB = q4[1];   // o pairs (4,5),(6,7)
                const ull* bk = bp + uv * 12;
                #pragma unroll
                for (int g = 0; g < 6; g++) {
                    ull bv = bk[g];      // LDS.64 broadcast (pre-duplicated)
                    acc[g][0] = fma2(qA.x, bv, acc[g][0]);
                    acc[g][1] = fma2(qA.y, bv, acc[g][1]);
                    acc[g][2] = fma2(qB.x, bv, acc[g][2]);
                    acc[g][3] = fma2(qB.y, bv, acc[g][3]);
                }
            }
        }
        // Store: group t lands at output g = t (interior) or (t+11)%12 (border).
        #pragma unroll
        for (int g = 0; g < 6; g++) {
            int t = gh * 6 + g;
            int gout = border ? (t == 0 ? 11 : t - 1) : t;
            float* ob8 = obase + (size_t)(gout * 8) * OSTRIDE;
            #pragma unroll
            for (int p = 0; p < 4; p++) {
                float lo, hi; unpack2(acc[g][p], lo, hi);
                ob8[(size_t)(2 * p)     * OSTRIDE] = lo;
                ob8[(size_t)(2 * p + 1) * OSTRIDE] = hi;
            }
        }
    }
}

// ---------------------------------------------------------------------------
extern "C" void kernel_launch(void* const* d_in, const int* in_sizes, int n_in,
                              void* d_out, int out_size)
{
    const float* x      = (const float*)d_in[0];
    const float* weight = (const float*)d_in[1];
    const float* bias   = (const float*)d_in[2];
    const float* basis  = (const float*)d_in[3];
    const int*   I      = (const int*)d_in[4];
    const int*   J      = (const int*)d_in[5];
    const int*   T      = (const int*)d_in[6];
    const int*   bb     = (const int*)d_in[7];
    float*       out    = (float*)d_out;

    const int smem1 = (KKN * OBN) * 4 + (KKN + 2) * 4;            // ~49.3 KB
    const int smem2 = 756 * 8 + (QTILE + 8) * 4;                  // ~77.8 KB
    cudaFuncSetAttribute(stage1_kernel, cudaFuncAttributeMaxDynamicSharedMemorySize, smem1);
    cudaFuncSetAttribute(stage2_kernel, cudaFuncAttributeMaxDynamicSharedMemorySize, smem2);

    stage1_kernel<<<NB, 320, smem1>>>(x, weight);
    zero_border_kernel<<<(OUT_ELEMS / 4 + 255) / 256, 256>>>((float4*)d_out);
    stage2_kernel<<<NB, 320, smem2>>>(bias, basis, I, J, T, bb, out);
}

// round 8
// speedup vs baseline: 1.7248x; 1.7248x over previous
#include <cuda_runtime.h>

// Problem constants (fixed by the reference):
// B=1, C=8, O=8, G=12, X=12, CH=8, CW=40, Xo=Yo=Zo=9
#define HWN   320      // CH*CW
#define NB    729      // 9*9*9 interior voxels
#define OBN   56       // O*7  (ob = o*7+b)
#define KKN   216      // C*27
#define GON   96       // G*O
#define VOX   1728     // 12*12*12
#define OSTRIDE (VOX*HWN)         // 552960, stride of one (g,o) plane
#define QTILE (OBN*HWN)           // 17920 floats per n
#define WSTRIDE 64                // padded k-stride in w_s (floats)

typedef unsigned long long ull;

__device__ __forceinline__ ull fma2(ull a, ull b, ull c) {
    ull d; asm("fma.rn.f32x2 %0, %1, %2, %3;" : "=l"(d) : "l"(a), "l"(b), "l"(c)); return d;
}
__device__ __forceinline__ ull pack2(float lo, float hi) {
    ull d; asm("mov.b64 %0, {%1, %2};" : "=l"(d) : "f"(lo), "f"(hi)); return d;
}
__device__ __forceinline__ void unpack2(ull v, float& lo, float& hi) {
    asm("mov.b64 {%0, %1}, %2;" : "=f"(lo), "=f"(hi) : "l"(v));
}

// Scratch: Q[n][b*320+hw][o] (52.2 MB). Stage2 reads all 8 o of a tap with
// 2 LDS.128 that reinterpret directly as (o0,o1),(o2,o3),... f32x2 pairs.
__device__ __align__(16) float g_Q[NB * QTILE];

// ---------------------------------------------------------------------------
// Stage 1: register-tiled GEMM  Q[ob, hw] = sum_k W[ob,k] * X[k, hw]  per n.
// Thread shape: 28 ob x 2 hw. Block 320 = obh(2) x hwp(160); warp-uniform obh.
// Per k: 7 LDS.128 (bcast W pairs) + 1 LDG.64 (x, coalesced) + 28 FFMA2.
// ---------------------------------------------------------------------------
extern "C" __global__ void __launch_bounds__(320, 2)
stage1_kernel(const float* __restrict__ x, const float* __restrict__ weight)
{
    extern __shared__ float sm1[];
    float* w_s    = sm1;                          // KKN*WSTRIDE floats (padded)
    int*   rowoff = (int*)(w_s + KKN * WSTRIDE);  // KKN+2 ints

    const int n   = blockIdx.x;
    const int tid = threadIdx.x;

    // weight[o][c][f][b] -> w_s[k*64 + obh*32 + (ob%28)], k = c*27+f, ob = o*7+b
    for (int idx = tid; idx < KKN * OBN; idx += 320) {
        int k = idx / OBN, ob = idx % OBN;
        int c = k / 27,    f  = k % 27;
        int o = ob / 7,    b  = ob % 7;
        int obh = ob / 28, obl = ob % 28;
        w_s[k * WSTRIDE + obh * 32 + obl] = weight[((o * 8 + c) * 27 + f) * 7 + b];
    }
    const int xi = n / 81, yj = (n / 9) % 9, zk = n % 9;
    for (int k = tid; k < KKN + 2; k += 320) {
        int kc = (k < KKN) ? k : (KKN - 1);
        int c = kc / 27, f = kc % 27;
        int fi = f / 9, fj = (f / 3) % 3, fk = f % 3;
        rowoff[k] = (((c * 12 + xi + fi) * 12 + (yj + fj)) * 12 + (zk + fk)) * HWN;
    }
    __syncthreads();

    const int obh = tid / 160;         // 0/1, uniform per warp (160 = 5 warps)
    const int hwb = (tid % 160) * 2;   // hw base, warp = 256B contiguous LDG.64

    ull acc[14][2];                    // [pair j][hw p]
    #pragma unroll
    for (int j = 0; j < 14; j++) { acc[j][0] = 0ULL; acc[j][1] = 0ULL; }

    float2 p0 = __ldg((const float2*)(x + rowoff[0] + hwb));
    float2 p1 = __ldg((const float2*)(x + rowoff[1] + hwb));
    for (int k = 0; k < KKN; k++) {
        float2 pn = __ldg((const float2*)(x + rowoff[k + 2] + hwb));
        ull xs0 = pack2(p0.x, p0.x), xs1 = pack2(p0.y, p0.y);
        const ulonglong2* wp = (const ulonglong2*)(w_s + k * WSTRIDE + obh * 32);
        #pragma unroll
        for (int j = 0; j < 7; j++) {
            ulonglong2 w2 = wp[j];                     // LDS.128 broadcast
            acc[2 * j    ][0] = fma2(w2.x, xs0, acc[2 * j    ][0]);
            acc[2 * j    ][1] = fma2(w2.x, xs1, acc[2 * j    ][1]);
            acc[2 * j + 1][0] = fma2(w2.y, xs0, acc[2 * j + 1][0]);
            acc[2 * j + 1][1] = fma2(w2.y, xs1, acc[2 * j + 1][1]);
        }
        p0 = p1; p1 = pn;
    }

    float accf[28][2];
    #pragma unroll
    for (int j = 0; j < 14; j++) {
        unpack2(acc[j][0], accf[2 * j][0], accf[2 * j + 1][0]);
        unpack2(acc[j][1], accf[2 * j][1], accf[2 * j + 1][1]);
    }

    // Store: g_Q[n][(b*320+hw)*8 + obh*4 + ol], local ob index = ol*7 + b.
    float* qn = g_Q + (size_t)n * QTILE + obh * 4;
    #pragma unroll
    for (int b = 0; b < 7; b++) {
        #pragma unroll
        for (int p = 0; p < 2; p++) {
            float4 v = make_float4(accf[b][p], accf[7 + b][p],
                                   accf[14 + b][p], accf[21 + b][p]);
            *reinterpret_cast<float4*>(qn + (b * HWN + hwb + p) * 8) = v;
        }
    }
}

// ---------------------------------------------------------------------------
// Stage 2 (fused direct-write + border zero): one block per output voxel.
// Border voxels: zero the 96x320 slab. Interior: thread = hw; compute the
// full 12g x 8o stack at clamped (ii,jj); T-gather is a static output-index
// rotation (T[g] = g interior, (g+1)%12 border); bias index = o.
// ---------------------------------------------------------------------------
extern "C" __global__ void __launch_bounds__(320, 2)
stage2_kernel(const float* __restrict__ bias,
              const float* __restrict__ basis,
              const int*   __restrict__ Iin,
              const int*   __restrict__ Jin,
              const int*   __restrict__ Tin,
              float*       __restrict__ out)
{
    extern __shared__ char sm2raw[];
    ull*   basP = (ull*)sm2raw;                  // [k=63][g=12] duplicated pairs
    float* Qs   = (float*)(basP + 756);          // 17920 floats, [b*320+pos][o]
    float* bsum = Qs + QTILE;                    // 8

    const int v   = blockIdx.x;                  // voxel 0..1727
    const int tid = threadIdx.x;
    const int xx = v / 144, yy = (v / 12) % 12, zz = v % 12;
    const bool interior = (xx >= 1 && xx <= 9 && yy >= 1 && yy <= 9 && zz >= 1 && zz <= 9);

    if (!interior) {
        // Zero the 96 (g,o)-planes of this voxel: 96*80 float4, coalesced.
        float4* out4 = (float4*)out;
        const size_t base4 = (size_t)v * (HWN / 4);
        for (int i = tid; i < GON * (HWN / 4); i += 320) {
            int go = i / (HWN / 4), q = i % (HWN / 4);
            out4[(size_t)go * (OSTRIDE / 4) + base4 + q] = make_float4(0.f, 0.f, 0.f, 0.f);
        }
        return;
    }

    const int n = (xx - 1) * 81 + (yy - 1) * 9 + (zz - 1);

    {
        const float4* src = (const float4*)(g_Q + (size_t)n * QTILE);
        float4* dst = (float4*)Qs;
        for (int i = tid; i < QTILE / 4; i += 320) dst[i] = src[i];
    }
    // basis[g][b][u][v] -> basP[(b*9+uv)*12 + g], duplicated into both halves.
    for (int i = tid; i < 756; i += 320) {
        float val = basis[i];
        int g = i / 63, k = i % 63;
        basP[k * 12 + g] = pack2(val, val);
    }
    if (tid < 8) {
        // bias_basis = tile(arange(O), G) -> bias index is o.
        float s = 0.f;
        for (int i = 0; i < 27; i++) s += bias[tid * 27 + i];
        bsum[tid] = s;
    }
    __syncthreads();

    const int ii = __ldg(Iin + tid) - 1;          // in [0,5]
    const int jj = __ldg(Jin + tid) - 1;          // in [0,37]
    const bool border = (__ldg(Tin + tid) != 0);  // T[g=0]: 1 on border, 0 inside

    const float* qbase = Qs + (ii * 40 + jj) * 8;
    ull binit[4];
    #pragma unroll
    for (int p = 0; p < 4; p++) binit[p] = pack2(bsum[2 * p], bsum[2 * p + 1]);

    float* obase = out + (size_t)v * HWN + tid;

    #pragma unroll 1
    for (int gh = 0; gh < 2; gh++) {
        ull acc[6][4];
        #pragma unroll
        for (int g = 0; g < 6; g++)
            #pragma unroll
            for (int p = 0; p < 4; p++) acc[g][p] = binit[p];

        #pragma unroll 1
        for (int b = 0; b < 7; b++) {
            const float* qb = qbase + b * (HWN * 8);
            const ull*   bp = basP + b * 108 + gh * 6;   // b*9*12
            #pragma unroll
            for (int uv = 0; uv < 9; uv++) {
                int u = uv / 3, vv = uv - u * 3;
                const ulonglong2* q4 = (const ulonglong2*)(qb + (u * 40 + vv) * 8);
                ulonglong2 qA = q4[0];   // o pairs (0,1),(2,3)
                ulonglong2 qB = q4[1];   // o pairs (4,5),(6,7)
                const ull* bk = bp + uv * 12;
                #pragma unroll
                for (int g = 0; g < 6; g++) {
                    ull bv = bk[g];      // LDS.64 broadcast (pre-duplicated)
                    acc[g][0] = fma2(qA.x, bv, acc[g][0]);
                    acc[g][1] = fma2(qA.y, bv, acc[g][1]);
                    acc[g][2] = fma2(qB.x, bv, acc[g][2]);
                    acc[g][3] = fma2(qB.y, bv, acc[g][3]);
                }
            }
        }
        // Group t lands at output g = t (interior) or (t+11)%12 (border).
        #pragma unroll
        for (int g = 0; g < 6; g++) {
            int t = gh * 6 + g;
            int gout = border ? (t == 0 ? 11 : t - 1) : t;
            float* ob8 = obase + (size_t)(gout * 8) * OSTRIDE;
            #pragma unroll
            for (int p = 0; p < 4; p++) {
                float lo, hi; unpack2(acc[g][p], lo, hi);
                ob8[(size_t)(2 * p)     * OSTRIDE] = lo;
                ob8[(size_t)(2 * p + 1) * OSTRIDE] = hi;
            }
        }
    }
}

// ---------------------------------------------------------------------------
extern "C" void kernel_launch(void* const* d_in, const int* in_sizes, int n_in,
                              void* d_out, int out_size)
{
    const float* x      = (const float*)d_in[0];
    const float* weight = (const float*)d_in[1];
    const float* bias   = (const float*)d_in[2];
    const float* basis  = (const float*)d_in[3];
    const int*   I      = (const int*)d_in[4];
    const int*   J      = (const int*)d_in[5];
    const int*   T      = (const int*)d_in[6];
    float*       out    = (float*)d_out;

    const int smem1 = KKN * WSTRIDE * 4 + (KKN + 2) * 4;          // ~56.2 KB
    const int smem2 = 756 * 8 + (QTILE + 8) * 4;                  // ~77.8 KB
    cudaFuncSetAttribute(stage1_kernel, cudaFuncAttributeMaxDynamicSharedMemorySize, smem1);
    cudaFuncSetAttribute(stage2_kernel, cudaFuncAttributeMaxDynamicSharedMemorySize, smem2);

    stage1_kernel<<<NB, 320, smem1>>>(x, weight);
    stage2_kernel<<<VOX, 320, smem2>>>(bias, basis, I, J, T, out);
}